// round 5
// baseline (speedup 1.0000x reference)
#include <cuda_runtime.h>
#include <cstdint>

#define N_NODES     200000
#define N_CLS       10
#define IDS_PER_CLS 20000
#define CENTER_BUDGET 2000
#define HOP_BUDGET  16384
#define CAND_CAP    8192
#define CCAP        4096
#define NODE_BLOCKS 196     // 196*1024 >= 200000

// ---------------------------------------------------------------------------
// Scratch (device globals — no allocations allowed)
// ---------------------------------------------------------------------------
struct Ctrl {
  unsigned keys[6];    // k_cls(0,1), k_h1(2,3), k_h2(4,5)
  unsigned nonzero;    // # finite candidate keys this hop
  unsigned cand_n;     // boundary-bucket candidate count
  unsigned need2;      // remaining winners to pick from boundary bucket
  unsigned thrT;       // threshold digit
  unsigned take_all;   // boundary bucket entirely selected
  int      is64;       // edge_index dtype: 1 = int64, 0 = int32
};

__device__ Ctrl               g_ctrl;
__device__ float              g_probs[N_NODES];
__device__ unsigned long long g_keys[N_NODES];
__device__ unsigned char      g_center[N_NODES];
__device__ unsigned char      g_retained[N_NODES];
__device__ unsigned char      g_nbr[N_NODES];
__device__ unsigned           g_hist[65536];
__device__ unsigned long long g_cand[CAND_CAP];
__device__ int                g_center_nodes[N_CLS * CENTER_BUDGET];

// ---------------------------------------------------------------------------
// threefry2x32 — matches JAX bit-for-bit (partitionable mode)
// ---------------------------------------------------------------------------
__device__ __forceinline__ void tf2x32(unsigned k0, unsigned k1,
                                       unsigned x0, unsigned x1,
                                       unsigned &o0, unsigned &o1) {
  unsigned ks2 = k0 ^ k1 ^ 0x1BD11BDAu;
  x0 += k0; x1 += k1;
#define TFR(r) { x0 += x1; x1 = (x1 << (r)) | (x1 >> (32 - (r))); x1 ^= x0; }
  TFR(13) TFR(15) TFR(26) TFR(6)
  x0 += k1;  x1 += ks2 + 1u;
  TFR(17) TFR(29) TFR(16) TFR(24)
  x0 += ks2; x1 += k0 + 2u;
  TFR(13) TFR(15) TFR(26) TFR(6)
  x0 += k0;  x1 += k1 + 3u;
  TFR(17) TFR(29) TFR(16) TFR(24)
  x0 += k1;  x1 += ks2 + 4u;
  TFR(13) TFR(15) TFR(26) TFR(6)
  x0 += ks2; x1 += k0 + 5u;
#undef TFR
  o0 = x0; o1 = x1;
}

__device__ __forceinline__ unsigned pbits32(unsigned k0, unsigned k1, unsigned i) {
  unsigned o0, o1;
  tf2x32(k0, k1, 0u, i, o0, o1);
  return o0 ^ o1;
}
__device__ __forceinline__ unsigned long long pbits64(unsigned k0, unsigned k1, unsigned i) {
  unsigned o0, o1;
  tf2x32(k0, k1, 0u, i, o0, o1);
  return (((unsigned long long)o0) << 32) | o1;
}

extern __shared__ unsigned char s_raw[];

// ---------------------------------------------------------------------------
// k_start: zero state + dtype detect + key splits
// ---------------------------------------------------------------------------
__global__ __launch_bounds__(1024) void k_start(const void* edge, long long E) {
  int i = blockIdx.x * blockDim.x + threadIdx.x;
  if (i < N_NODES) {
    g_probs[i] = 0.f; g_center[i] = 0; g_retained[i] = 0; g_nbr[i] = 0;
  }
  if (i < 65536) g_hist[i] = 0;
  if (i == 0) {
    const long long* p = (const long long*)edge;
    int ok = 1;
    long long lim = (E < 128) ? E : 128;
    for (long long t = 0; t < lim; t++) {
      long long v = p[t];
      if (v < 0 || v >= N_NODES) { ok = 0; break; }
    }
    g_ctrl.is64 = ok;
    unsigned o0, o1;
    tf2x32(0u, 42u, 0u, 0u, o0, o1); g_ctrl.keys[0] = o0; g_ctrl.keys[1] = o1;
    tf2x32(0u, 42u, 0u, 1u, o0, o1); g_ctrl.keys[2] = o0; g_ctrl.keys[3] = o1;
    tf2x32(0u, 42u, 0u, 2u, o0, o1); g_ctrl.keys[4] = o0; g_ctrl.keys[5] = o1;
    g_ctrl.nonzero = 0; g_ctrl.cand_n = 0;
  }
}

// ---------------------------------------------------------------------------
// Center sampling: rank-based selection (validated bit-exact in R3).
// ---------------------------------------------------------------------------
__global__ __launch_bounds__(1024) void k_centers() {
  unsigned long long* skey = (unsigned long long*)s_raw;       // CCAP*8
  unsigned*           sjdx = (unsigned*)(skey + CCAP);         // CCAP*4
  unsigned*           hist = sjdx + CCAP;                      // CCAP*4
  __shared__ unsigned s_cnt;
  __shared__ int      s_T;
  __shared__ unsigned part[1024];

  int c = blockIdx.x, tid = threadIdx.x;
  int is64 = g_ctrl.is64;
  unsigned kc0 = g_ctrl.keys[0], kc1 = g_ctrl.keys[1];

  for (int b = tid; b < CCAP; b += 1024) hist[b] = 0;
  if (tid == 0) s_cnt = 0;
  __syncthreads();

  for (int j = tid; j < IDS_PER_CLS; j += 1024) {
    unsigned m = (unsigned)(c * IDS_PER_CLS + j);
    unsigned long long key; unsigned b;
    if (is64) {
      unsigned long long mant = pbits64(kc0, kc1, m) >> 12;
      key = mant;
      b = (unsigned)(mant >> 40);
    } else {
      unsigned man = pbits32(kc0, kc1, m) >> 9;
      key = (((unsigned long long)man) << 32) | (unsigned)j;
      b = man >> 11;
    }
    g_keys[m] = key;
    atomicAdd(&hist[b], 1u);
  }
  __syncthreads();

  // smallest T with cum(<=T) >= 2000
  unsigned ps = 0;
  for (int b = tid * 4; b < tid * 4 + 4; b++) ps += hist[b];
  part[tid] = ps;
  __syncthreads();
  if (tid == 0) {
    unsigned acc = 0; int T = CCAP - 1;
    for (int t = 0; t < 1024; t++) {
      if (acc + part[t] >= CENTER_BUDGET) {
        for (int b = t * 4; b < t * 4 + 4; b++) {
          acc += hist[b];
          if (acc >= CENTER_BUDGET) { T = b; break; }
        }
        break;
      }
      acc += part[t];
    }
    s_T = T;
  }
  __syncthreads();
  int T = s_T;

  // collect candidates (bucket <= T) unordered
  for (int j = tid; j < IDS_PER_CLS; j += 1024) {
    int m = c * IDS_PER_CLS + j;
    unsigned long long key = g_keys[m];
    unsigned b = is64 ? (unsigned)(key >> 40) : (unsigned)(key >> 43);
    if ((int)b <= T) {
      unsigned pos = atomicAdd(&s_cnt, 1u);
      if (pos < CCAP) { skey[pos] = key; sjdx[pos] = (unsigned)j; }
    }
  }
  __syncthreads();
  int cnt = (int)((s_cnt < CCAP) ? s_cnt : CCAP);

  // rank-based selection: rank = #(key,j) pairs strictly smaller
  for (int p = tid; p < cnt; p += 1024) {
    unsigned long long k = skey[p];
    unsigned j = sjdx[p];
    int rank = 0;
    for (int i = 0; i < cnt; i++) {
      unsigned long long ki = skey[i];
      unsigned ji = sjdx[i];
      rank += (ki < k) || (ki == k && ji < j);
    }
    if (rank < CENTER_BUDGET) {
      int node = c * IDS_PER_CLS + (int)j;     // ids_per_cls == arange
      g_center_nodes[c * CENTER_BUDGET + rank] = node;
      g_center[node] = 1;
      g_retained[node] = 1;
    }
  }
}

// ---------------------------------------------------------------------------
// Fused edge pass: degree segment-sum + neighbor mask. 4 edges/thread.
// ---------------------------------------------------------------------------
__global__ __launch_bounds__(256) void k_edges(const void* edge, const float* w, long long E) {
  long long base = ((long long)blockIdx.x * 256 + threadIdx.x) * 4;
  if (base >= E) return;
  int is64 = g_ctrl.is64;
  if (base + 3 < E) {
    int s[4], d[4];
    if (is64) {
      const ulonglong2* ps = (const ulonglong2*)((const long long*)edge + base);
      const ulonglong2* pd = (const ulonglong2*)((const long long*)edge + E + base);
      ulonglong2 s01 = ps[0], s23 = ps[1];
      ulonglong2 d01 = pd[0], d23 = pd[1];
      s[0]=(int)s01.x; s[1]=(int)s01.y; s[2]=(int)s23.x; s[3]=(int)s23.y;
      d[0]=(int)d01.x; d[1]=(int)d01.y; d[2]=(int)d23.x; d[3]=(int)d23.y;
    } else {
      const int4* ps = (const int4*)((const int*)edge + base);
      const int4* pd = (const int4*)((const int*)edge + E + base);
      int4 sv = ps[0], dv = pd[0];
      s[0]=sv.x; s[1]=sv.y; s[2]=sv.z; s[3]=sv.w;
      d[0]=dv.x; d[1]=dv.y; d[2]=dv.z; d[3]=dv.w;
    }
    float4 wv = *(const float4*)(w + base);
    atomicAdd(&g_probs[d[0]], wv.x);
    atomicAdd(&g_probs[d[1]], wv.y);
    atomicAdd(&g_probs[d[2]], wv.z);
    atomicAdd(&g_probs[d[3]], wv.w);
    unsigned char c0 = g_center[s[0]], c1 = g_center[s[1]];
    unsigned char c2 = g_center[s[2]], c3 = g_center[s[3]];
    if (c0) g_nbr[d[0]] = 1;
    if (c1) g_nbr[d[1]] = 1;
    if (c2) g_nbr[d[2]] = 1;
    if (c3) g_nbr[d[3]] = 1;
  } else {
    for (long long i = base; i < E; i++) {
      int s, d;
      if (is64) {
        const long long* p = (const long long*)edge;
        s = (int)p[i]; d = (int)p[E + i];
      } else {
        const int* p = (const int*)edge;
        s = p[i]; d = p[E + i];
      }
      atomicAdd(&g_probs[d], w[i]);
      if (g_center[s]) g_nbr[d] = 1;
    }
  }
}

// ---------------------------------------------------------------------------
// Hop keys (bit-exact gumbel, validated). No fences — kernel boundary orders.
// ---------------------------------------------------------------------------
__global__ __launch_bounds__(1024) void k_build(int h) {
  int n = blockIdx.x * blockDim.x + threadIdx.x;
  unsigned long long kk = 0;
  if (n < N_NODES) {
    unsigned kh0 = g_ctrl.keys[2 + 2 * h], kh1 = g_ctrl.keys[3 + 2 * h];
    unsigned bits = pbits32(kh0, kh1, (unsigned)n);
    float ur = __uint_as_float((bits >> 9) | 0x3f800000u) - 1.0f;
    float u  = fmaxf(1.17549435e-38f, ur + 1.17549435e-38f);
    float g  = -logf(-logf(u));
    float v  = logf(g_probs[n]) + g;
    bool cand = g_nbr[n] && !g_retained[n];
    if (cand && isfinite(v)) {
      unsigned b   = __float_as_uint(v);
      unsigned ord = b ^ ((b & 0x80000000u) ? 0xFFFFFFFFu : 0x80000000u);
      kk = (((unsigned long long)ord) << 32) | (0xFFFFFFFFu - (unsigned)n);
      atomicAdd(&g_hist[(unsigned)(kk >> 48)], 1u);
    }
    g_keys[n] = kk;
  }
  unsigned act = __ballot_sync(0xFFFFFFFFu, kk != 0ULL);
  if ((threadIdx.x & 31) == 0 && act)
    atomicAdd(&g_ctrl.nonzero, (unsigned)__popc(act));
}

__global__ __launch_bounds__(1024) void k_thresh() {
  __shared__ unsigned part[1024];
  int tid = threadIdx.x;
  unsigned ps = 0;
  for (int b = tid * 64; b < tid * 64 + 64; b++) ps += g_hist[b];
  part[tid] = ps;
  __syncthreads();
  if (tid == 0) {
    unsigned nz = g_ctrl.nonzero;
    unsigned need = (nz < HOP_BUDGET) ? nz : HOP_BUDGET;
    unsigned acc = 0, above = 0; int T = 0;
    for (int t = 1023; t >= 0; t--) {
      if (acc + part[t] >= need) {
        for (int b = t * 64 + 63; b >= t * 64; b--) {
          if (acc + g_hist[b] >= need) { T = b; above = acc; break; }
          acc += g_hist[b];
        }
        break;
      }
      acc += part[t];
    }
    g_ctrl.thrT = (unsigned)T;
    unsigned need2 = need - above;
    g_ctrl.need2 = need2;
    g_ctrl.take_all = (need2 >= g_hist[T]) ? 1u : 0u;
    g_ctrl.cand_n = 0;
    g_ctrl.nonzero = 0;          // ready for next hop
  }
}

// ---------------------------------------------------------------------------
// Scatter winners + collect boundary bucket; re-zero hist for next hop.
// ---------------------------------------------------------------------------
__global__ __launch_bounds__(1024) void k_scatter() {
  int n = blockIdx.x * blockDim.x + threadIdx.x;
  unsigned T = g_ctrl.thrT;
  unsigned take_all = g_ctrl.take_all;
  if (n < 65536) g_hist[n] = 0;
  if (n >= N_NODES) return;
  unsigned long long kk = g_keys[n];
  if (!kk) return;
  unsigned dg = (unsigned)(kk >> 48);
  if (dg > T) {
    g_retained[n] = 1;
  } else if (dg == T) {
    if (take_all) {
      g_retained[n] = 1;
    } else {
      unsigned pos = atomicAdd(&g_ctrl.cand_n, 1u);
      if (pos < CAND_CAP) g_cand[pos] = kk;
    }
  }
}

// ---------------------------------------------------------------------------
// Boundary-bucket top-need2 via rank (keys unique). One block; cnt is tiny
// (expected ~nonzero/65536 per bucket), so O(cnt^2/1024) is trivial.
// ---------------------------------------------------------------------------
__global__ __launch_bounds__(1024) void k_final() {
  unsigned long long* fkey = (unsigned long long*)s_raw;   // CAND_CAP*8
  if (g_ctrl.take_all) return;
  unsigned need2 = g_ctrl.need2;
  if (need2 == 0) return;
  int cnt = (int)((g_ctrl.cand_n < CAND_CAP) ? g_ctrl.cand_n : CAND_CAP);
  for (int i = threadIdx.x; i < cnt; i += 1024) fkey[i] = g_cand[i];
  __syncthreads();
  for (int p = threadIdx.x; p < cnt; p += 1024) {
    unsigned long long myk = fkey[p];
    int rank = 0;
    for (int i = 0; i < cnt; i++)
      rank += (fkey[i] > myk);
    if (rank < (int)need2) {
      unsigned node = 0xFFFFFFFFu - (unsigned)(myk & 0xFFFFFFFFu);
      g_retained[node] = 1;
    }
  }
}

// ---------------------------------------------------------------------------
// Output: f32 [center_nodes | retained | masked_probs]; branch on out_size.
// ---------------------------------------------------------------------------
__global__ void k_out(float* out, long long out_size) {
  long long i = (long long)blockIdx.x * blockDim.x + threadIdx.x;
  if (i >= out_size) return;
  float v;
  if (out_size == 420000) {
    if (i < 20000)        v = (float)g_center_nodes[i];
    else if (i < 220000)  v = g_retained[i - 20000] ? 1.f : 0.f;
    else                  v = g_retained[i - 220000] ? g_probs[i - 220000] : 0.f;
  } else if (out_size == 400000) {
    if (i < 200000)       v = g_retained[i] ? 1.f : 0.f;
    else                  v = g_retained[i - 200000] ? g_probs[i - 200000] : 0.f;
  } else if (out_size == 200000) {
    v = g_retained[i] ? g_probs[i] : 0.f;
  } else if (out_size == 20000) {
    v = (float)g_center_nodes[i];
  } else {
    v = 0.f;
  }
  out[i] = v;
}

// ---------------------------------------------------------------------------
extern "C" void kernel_launch(void* const* d_in, const int* in_sizes, int n_in,
                              void* d_out, int out_size) {
  const void* edge = d_in[0];
  const float* w = (const float*)d_in[1];
  long long E = (long long)in_sizes[0] / 2;

  cudaFuncSetAttribute(k_centers, cudaFuncAttributeMaxDynamicSharedMemorySize,
                       CCAP * 8 + CCAP * 4 + CCAP * 4);
  cudaFuncSetAttribute(k_final, cudaFuncAttributeMaxDynamicSharedMemorySize,
                       CAND_CAP * 8);

  k_start<<<NODE_BLOCKS, 1024>>>(edge, E);
  k_centers<<<N_CLS, 1024, CCAP * 8 + CCAP * 4 + CCAP * 4>>>();
  k_edges<<<(unsigned)((E + 1023) / 1024), 256>>>(edge, w, E);
  for (int h = 0; h < 2; h++) {
    k_build<<<NODE_BLOCKS, 1024>>>(h);
    k_thresh<<<1, 1024>>>();
    k_scatter<<<NODE_BLOCKS, 1024>>>();
    k_final<<<1, 1024, CAND_CAP * 8>>>();
  }
  k_out<<<((long long)out_size + 255) / 256, 256>>>((float*)d_out, (long long)out_size);
}

// round 7
// speedup vs baseline: 1.4509x; 1.4509x over previous
#include <cuda_runtime.h>
#include <cstdint>

#define N_NODES     200000
#define N_CLS       10
#define IDS_PER_CLS 20000
#define CENTER_BUDGET 2000
#define HOP_BUDGET  16384
#define CAND_CAP    16384
#define CCAP        4096
#define NODE_BLOCKS 196     // 196*1024 >= 200000

// ---------------------------------------------------------------------------
// Scratch (device globals — no allocations allowed)
// ---------------------------------------------------------------------------
struct Ctrl {
  unsigned keys[6];    // k_cls(0,1), k_h1(2,3), k_h2(4,5)
  unsigned nonzero;    // # finite candidate keys this hop
  unsigned cand_n;     // boundary-bucket candidate count
  unsigned need2;      // remaining winners to pick from boundary bucket
  unsigned thrT;       // threshold digit (level 1, bits 63:48)
  unsigned take_all;   // boundary bucket entirely selected
  int      is64;       // edge_index dtype: 1 = int64, 0 = int32
};

__device__ Ctrl               g_ctrl;
__device__ float              g_probs[N_NODES];
__device__ unsigned long long g_keys[N_NODES];
__device__ unsigned char      g_center[N_NODES];
__device__ unsigned char      g_retained[N_NODES];
__device__ unsigned char      g_nbr[N_NODES];
__device__ unsigned           g_hist[65536];
__device__ unsigned long long g_cand[CAND_CAP];
__device__ int                g_center_nodes[N_CLS * CENTER_BUDGET];

// ---------------------------------------------------------------------------
// threefry2x32 — matches JAX bit-for-bit (partitionable mode)
// ---------------------------------------------------------------------------
__device__ __forceinline__ void tf2x32(unsigned k0, unsigned k1,
                                       unsigned x0, unsigned x1,
                                       unsigned &o0, unsigned &o1) {
  unsigned ks2 = k0 ^ k1 ^ 0x1BD11BDAu;
  x0 += k0; x1 += k1;
#define TFR(r) { x0 += x1; x1 = (x1 << (r)) | (x1 >> (32 - (r))); x1 ^= x0; }
  TFR(13) TFR(15) TFR(26) TFR(6)
  x0 += k1;  x1 += ks2 + 1u;
  TFR(17) TFR(29) TFR(16) TFR(24)
  x0 += ks2; x1 += k0 + 2u;
  TFR(13) TFR(15) TFR(26) TFR(6)
  x0 += k0;  x1 += k1 + 3u;
  TFR(17) TFR(29) TFR(16) TFR(24)
  x0 += k1;  x1 += ks2 + 4u;
  TFR(13) TFR(15) TFR(26) TFR(6)
  x0 += ks2; x1 += k0 + 5u;
#undef TFR
  o0 = x0; o1 = x1;
}

__device__ __forceinline__ unsigned pbits32(unsigned k0, unsigned k1, unsigned i) {
  unsigned o0, o1;
  tf2x32(k0, k1, 0u, i, o0, o1);
  return o0 ^ o1;
}
__device__ __forceinline__ unsigned long long pbits64(unsigned k0, unsigned k1, unsigned i) {
  unsigned o0, o1;
  tf2x32(k0, k1, 0u, i, o0, o1);
  return (((unsigned long long)o0) << 32) | o1;
}

extern __shared__ unsigned char s_raw[];

// ---------------------------------------------------------------------------
// k_start: zero state + parallel dtype detect + key splits
// ---------------------------------------------------------------------------
__global__ __launch_bounds__(1024) void k_start(const void* edge, long long E) {
  __shared__ int s_bad;
  int i = blockIdx.x * blockDim.x + threadIdx.x;
  if (i < N_NODES) {
    g_probs[i] = 0.f; g_center[i] = 0; g_retained[i] = 0; g_nbr[i] = 0;
  }
  if (i < 65536) g_hist[i] = 0;
  if (blockIdx.x == 0) {
    if (threadIdx.x == 0) s_bad = 0;
    __syncthreads();
    long long lim = (E < 128) ? E : 128;
    if (threadIdx.x < 128 && (long long)threadIdx.x < lim) {
      long long v = ((const long long*)edge)[threadIdx.x];
      if (v < 0 || v >= N_NODES) atomicOr(&s_bad, 1);
    }
    __syncthreads();
    if (threadIdx.x == 0) {
      g_ctrl.is64 = s_bad ? 0 : 1;
      unsigned o0, o1;
      tf2x32(0u, 42u, 0u, 0u, o0, o1); g_ctrl.keys[0] = o0; g_ctrl.keys[1] = o1;
      tf2x32(0u, 42u, 0u, 1u, o0, o1); g_ctrl.keys[2] = o0; g_ctrl.keys[3] = o1;
      tf2x32(0u, 42u, 0u, 2u, o0, o1); g_ctrl.keys[4] = o0; g_ctrl.keys[5] = o1;
      g_ctrl.nonzero = 0; g_ctrl.cand_n = 0;
    }
  }
}

// ---------------------------------------------------------------------------
// Center sampling: rank-based selection (validated bit-exact; cnt ~2005 fixed)
// ---------------------------------------------------------------------------
__global__ __launch_bounds__(1024) void k_centers() {
  unsigned long long* skey = (unsigned long long*)s_raw;       // CCAP*8
  unsigned*           sjdx = (unsigned*)(skey + CCAP);         // CCAP*4
  unsigned*           hist = sjdx + CCAP;                      // CCAP*4
  __shared__ unsigned s_cnt;
  __shared__ int      s_T;
  __shared__ unsigned part[1024];

  int c = blockIdx.x, tid = threadIdx.x;
  int is64 = g_ctrl.is64;
  unsigned kc0 = g_ctrl.keys[0], kc1 = g_ctrl.keys[1];

  for (int b = tid; b < CCAP; b += 1024) hist[b] = 0;
  if (tid == 0) s_cnt = 0;
  __syncthreads();

  for (int j = tid; j < IDS_PER_CLS; j += 1024) {
    unsigned m = (unsigned)(c * IDS_PER_CLS + j);
    unsigned long long key; unsigned b;
    if (is64) {
      unsigned long long mant = pbits64(kc0, kc1, m) >> 12;
      key = mant;
      b = (unsigned)(mant >> 40);
    } else {
      unsigned man = pbits32(kc0, kc1, m) >> 9;
      key = (((unsigned long long)man) << 32) | (unsigned)j;
      b = man >> 11;
    }
    g_keys[m] = key;
    atomicAdd(&hist[b], 1u);
  }
  __syncthreads();

  // smallest T with cum(<=T) >= 2000
  unsigned ps = 0;
  for (int b = tid * 4; b < tid * 4 + 4; b++) ps += hist[b];
  part[tid] = ps;
  __syncthreads();
  if (tid == 0) {
    unsigned acc = 0; int T = CCAP - 1;
    for (int t = 0; t < 1024; t++) {
      if (acc + part[t] >= CENTER_BUDGET) {
        for (int b = t * 4; b < t * 4 + 4; b++) {
          acc += hist[b];
          if (acc >= CENTER_BUDGET) { T = b; break; }
        }
        break;
      }
      acc += part[t];
    }
    s_T = T;
  }
  __syncthreads();
  int T = s_T;

  // collect candidates (bucket <= T) unordered
  for (int j = tid; j < IDS_PER_CLS; j += 1024) {
    int m = c * IDS_PER_CLS + j;
    unsigned long long key = g_keys[m];
    unsigned b = is64 ? (unsigned)(key >> 40) : (unsigned)(key >> 43);
    if ((int)b <= T) {
      unsigned pos = atomicAdd(&s_cnt, 1u);
      if (pos < CCAP) { skey[pos] = key; sjdx[pos] = (unsigned)j; }
    }
  }
  __syncthreads();
  int cnt = (int)((s_cnt < CCAP) ? s_cnt : CCAP);

  // rank-based selection: rank = #(key,j) pairs strictly smaller
  for (int p = tid; p < cnt; p += 1024) {
    unsigned long long k = skey[p];
    unsigned j = sjdx[p];
    int rank = 0;
    for (int i = 0; i < cnt; i++) {
      unsigned long long ki = skey[i];
      unsigned ji = sjdx[i];
      rank += (ki < k) || (ki == k && ji < j);
    }
    if (rank < CENTER_BUDGET) {
      int node = c * IDS_PER_CLS + (int)j;     // ids_per_cls == arange
      g_center_nodes[c * CENTER_BUDGET + rank] = node;
      g_center[node] = 1;
      g_retained[node] = 1;
    }
  }
}

// ---------------------------------------------------------------------------
// Fused edge pass: degree segment-sum + neighbor mask. 4 edges/thread.
// ---------------------------------------------------------------------------
__global__ __launch_bounds__(256) void k_edges(const void* edge, const float* w, long long E) {
  long long base = ((long long)blockIdx.x * 256 + threadIdx.x) * 4;
  if (base >= E) return;
  int is64 = g_ctrl.is64;
  if (base + 3 < E) {
    int s[4], d[4];
    if (is64) {
      const ulonglong2* ps = (const ulonglong2*)((const long long*)edge + base);
      const ulonglong2* pd = (const ulonglong2*)((const long long*)edge + E + base);
      ulonglong2 s01 = ps[0], s23 = ps[1];
      ulonglong2 d01 = pd[0], d23 = pd[1];
      s[0]=(int)s01.x; s[1]=(int)s01.y; s[2]=(int)s23.x; s[3]=(int)s23.y;
      d[0]=(int)d01.x; d[1]=(int)d01.y; d[2]=(int)d23.x; d[3]=(int)d23.y;
    } else {
      const int4* ps = (const int4*)((const int*)edge + base);
      const int4* pd = (const int4*)((const int*)edge + E + base);
      int4 sv = ps[0], dv = pd[0];
      s[0]=sv.x; s[1]=sv.y; s[2]=sv.z; s[3]=sv.w;
      d[0]=dv.x; d[1]=dv.y; d[2]=dv.z; d[3]=dv.w;
    }
    float4 wv = *(const float4*)(w + base);
    atomicAdd(&g_probs[d[0]], wv.x);
    atomicAdd(&g_probs[d[1]], wv.y);
    atomicAdd(&g_probs[d[2]], wv.z);
    atomicAdd(&g_probs[d[3]], wv.w);
    unsigned char c0 = g_center[s[0]], c1 = g_center[s[1]];
    unsigned char c2 = g_center[s[2]], c3 = g_center[s[3]];
    if (c0) g_nbr[d[0]] = 1;
    if (c1) g_nbr[d[1]] = 1;
    if (c2) g_nbr[d[2]] = 1;
    if (c3) g_nbr[d[3]] = 1;
  } else {
    for (long long i = base; i < E; i++) {
      int s, d;
      if (is64) {
        const long long* p = (const long long*)edge;
        s = (int)p[i]; d = (int)p[E + i];
      } else {
        const int* p = (const int*)edge;
        s = p[i]; d = p[E + i];
      }
      atomicAdd(&g_probs[d], w[i]);
      if (g_center[s]) g_nbr[d] = 1;
    }
  }
}

// ---------------------------------------------------------------------------
// Hop keys (bit-exact gumbel, validated).
// key64 = ord(val)<<32 | (0xFFFFFFFF - n)  (value desc, idx asc)
// ---------------------------------------------------------------------------
__global__ __launch_bounds__(1024) void k_build(int h) {
  int n = blockIdx.x * blockDim.x + threadIdx.x;
  unsigned long long kk = 0;
  if (n < N_NODES) {
    unsigned kh0 = g_ctrl.keys[2 + 2 * h], kh1 = g_ctrl.keys[3 + 2 * h];
    unsigned bits = pbits32(kh0, kh1, (unsigned)n);
    float ur = __uint_as_float((bits >> 9) | 0x3f800000u) - 1.0f;
    float u  = fmaxf(1.17549435e-38f, ur + 1.17549435e-38f);
    float g  = -logf(-logf(u));
    float v  = logf(g_probs[n]) + g;
    bool cand = g_nbr[n] && !g_retained[n];
    if (cand && isfinite(v)) {
      unsigned b   = __float_as_uint(v);
      unsigned ord = b ^ ((b & 0x80000000u) ? 0xFFFFFFFFu : 0x80000000u);
      kk = (((unsigned long long)ord) << 32) | (0xFFFFFFFFu - (unsigned)n);
      atomicAdd(&g_hist[(unsigned)(kk >> 48)], 1u);
    }
    g_keys[n] = kk;
  }
  unsigned act = __ballot_sync(0xFFFFFFFFu, kk != 0ULL);
  if ((threadIdx.x & 31) == 0 && act)
    atomicAdd(&g_ctrl.nonzero, (unsigned)__popc(act));
}

__global__ __launch_bounds__(1024) void k_thresh() {
  __shared__ unsigned part[1024];
  int tid = threadIdx.x;
  unsigned ps = 0;
  for (int b = tid * 64; b < tid * 64 + 64; b++) ps += g_hist[b];
  part[tid] = ps;
  __syncthreads();
  if (tid == 0) {
    unsigned nz = g_ctrl.nonzero;
    unsigned need = (nz < HOP_BUDGET) ? nz : HOP_BUDGET;
    unsigned acc = 0, above = 0; int T = 0;
    for (int t = 1023; t >= 0; t--) {
      if (acc + part[t] >= need) {
        for (int b = t * 64 + 63; b >= t * 64; b--) {
          if (acc + g_hist[b] >= need) { T = b; above = acc; break; }
          acc += g_hist[b];
        }
        break;
      }
      acc += part[t];
    }
    g_ctrl.thrT = (unsigned)T;
    unsigned need2 = need - above;
    g_ctrl.need2 = need2;
    g_ctrl.take_all = (need2 >= g_hist[T]) ? 1u : 0u;
    g_ctrl.cand_n = 0;
    g_ctrl.nonzero = 0;          // ready for next hop
  }
}

// ---------------------------------------------------------------------------
// Scatter winners + collect boundary bucket; re-zero hist for next hop.
// ---------------------------------------------------------------------------
__global__ __launch_bounds__(1024) void k_scatter() {
  int n = blockIdx.x * blockDim.x + threadIdx.x;
  unsigned T = g_ctrl.thrT;
  unsigned take_all = g_ctrl.take_all;
  if (n < 65536) g_hist[n] = 0;
  if (n >= N_NODES) return;
  unsigned long long kk = g_keys[n];
  if (!kk) return;
  unsigned dg = (unsigned)(kk >> 48);
  if (dg > T) {
    g_retained[n] = 1;
  } else if (dg == T) {
    if (take_all) {
      g_retained[n] = 1;
    } else {
      unsigned pos = atomicAdd(&g_ctrl.cand_n, 1u);
      if (pos < CAND_CAP) g_cand[pos] = kk;
    }
  }
}

// ---------------------------------------------------------------------------
// Boundary bucket: two-level refine. Level-2 histogram on bits [47:36]
// (4096 buckets), retain digits > T2, rank only the ==T2 group (tiny).
// ---------------------------------------------------------------------------
__global__ __launch_bounds__(1024) void k_final() {
  __shared__ unsigned hist2[4096];
  __shared__ unsigned part[1024];
  __shared__ int      s_T2;
  __shared__ unsigned s_need3, s_scnt;
  __shared__ unsigned long long skey[1024];

  if (g_ctrl.take_all) return;
  unsigned need2 = g_ctrl.need2;
  if (need2 == 0) return;
  unsigned cn = g_ctrl.cand_n;
  int cnt = (int)((cn < CAND_CAP) ? cn : CAND_CAP);
  int tid = threadIdx.x;

  for (int b = tid; b < 4096; b += 1024) hist2[b] = 0;
  if (tid == 0) s_scnt = 0;
  __syncthreads();

  for (int i = tid; i < cnt; i += 1024)
    atomicAdd(&hist2[(unsigned)(g_cand[i] >> 36) & 0xFFFu], 1u);
  __syncthreads();

  unsigned ps = 0;
  for (int b = tid * 4; b < tid * 4 + 4; b++) ps += hist2[b];
  part[tid] = ps;
  __syncthreads();
  if (tid == 0) {
    unsigned acc = 0, above = 0; int T2 = 0;
    for (int t = 1023; t >= 0; t--) {
      if (acc + part[t] >= need2) {
        for (int b = t * 4 + 3; b >= t * 4; b--) {
          if (acc + hist2[b] >= need2) { T2 = b; above = acc; break; }
          acc += hist2[b];
        }
        break;
      }
      acc += part[t];
    }
    s_T2 = T2;
    s_need3 = need2 - above;
  }
  __syncthreads();
  int T2 = s_T2;
  unsigned need3 = s_need3;

  for (int i = tid; i < cnt; i += 1024) {
    unsigned long long k = g_cand[i];
    int d2 = (int)((k >> 36) & 0xFFFu);
    if (d2 > T2) {
      g_retained[0xFFFFFFFFu - (unsigned)(k & 0xFFFFFFFFu)] = 1;
    } else if (d2 == T2) {
      unsigned p = atomicAdd(&s_scnt, 1u);
      if (p < 1024) skey[p] = k;
    }
  }
  __syncthreads();
  int c2 = (int)((s_scnt < 1024u) ? s_scnt : 1024u);

  for (int p = tid; p < c2; p += 1024) {
    unsigned long long myk = skey[p];
    int rank = 0;
    for (int i = 0; i < c2; i++)
      rank += (skey[i] > myk);                 // keys unique (idx in low bits)
    if (rank < (int)need3)
      g_retained[0xFFFFFFFFu - (unsigned)(myk & 0xFFFFFFFFu)] = 1;
  }
}

// ---------------------------------------------------------------------------
// Output: f32 [center_nodes | retained | masked_probs]; branch on out_size.
// ---------------------------------------------------------------------------
__global__ void k_out(float* out, long long out_size) {
  long long i = (long long)blockIdx.x * blockDim.x + threadIdx.x;
  if (i >= out_size) return;
  float v;
  if (out_size == 420000) {
    if (i < 20000)        v = (float)g_center_nodes[i];
    else if (i < 220000)  v = g_retained[i - 20000] ? 1.f : 0.f;
    else                  v = g_retained[i - 220000] ? g_probs[i - 220000] : 0.f;
  } else if (out_size == 400000) {
    if (i < 200000)       v = g_retained[i] ? 1.f : 0.f;
    else                  v = g_retained[i - 200000] ? g_probs[i - 200000] : 0.f;
  } else if (out_size == 200000) {
    v = g_retained[i] ? g_probs[i] : 0.f;
  } else if (out_size == 20000) {
    v = (float)g_center_nodes[i];
  } else {
    v = 0.f;
  }
  out[i] = v;
}

// ---------------------------------------------------------------------------
extern "C" void kernel_launch(void* const* d_in, const int* in_sizes, int n_in,
                              void* d_out, int out_size) {
  const void* edge = d_in[0];
  const float* w = (const float*)d_in[1];
  long long E = (long long)in_sizes[0] / 2;

  cudaFuncSetAttribute(k_centers, cudaFuncAttributeMaxDynamicSharedMemorySize,
                       CCAP * 8 + CCAP * 4 + CCAP * 4);

  k_start<<<NODE_BLOCKS, 1024>>>(edge, E);
  k_centers<<<N_CLS, 1024, CCAP * 8 + CCAP * 4 + CCAP * 4>>>();
  k_edges<<<(unsigned)((E + 1023) / 1024), 256>>>(edge, w, E);
  for (int h = 0; h < 2; h++) {
    k_build<<<NODE_BLOCKS, 1024>>>(h);
    k_thresh<<<1, 1024>>>();
    k_scatter<<<NODE_BLOCKS, 1024>>>();
    k_final<<<1, 1024>>>();
  }
  k_out<<<((long long)out_size + 255) / 256, 256>>>((float*)d_out, (long long)out_size);
}

// round 8
// speedup vs baseline: 1.5564x; 1.0727x over previous
#include <cuda_runtime.h>
#include <cstdint>

#define N_NODES     200000
#define N_CLS       10
#define IDS_PER_CLS 20000
#define CENTER_BUDGET 2000
#define HOP_BUDGET  16384
#define CAND_CAP    16384
#define CCAP        4096
#define NODE_BLOCKS 196     // 196*1024 >= 200000

struct Ctrl {
  unsigned keys[6];
  unsigned cand_n;
  unsigned need2;
  unsigned thrT;       // level-1 threshold digit (bits 63:48); 0xFFFFFFFF = none
  unsigned take_all;
  int      is64;
};

__device__ Ctrl               g_ctrl;
__device__ unsigned           g_done[4];
__device__ float              g_probs[N_NODES];
__device__ unsigned long long g_keys[N_NODES];
__device__ unsigned char      g_center[N_NODES];
__device__ unsigned char      g_retained[N_NODES];
__device__ unsigned char      g_nbr[N_NODES];
__device__ unsigned           g_hist[65536];
__device__ unsigned long long g_cand[CAND_CAP];
__device__ int                g_center_nodes[N_CLS * CENTER_BUDGET];

// ---------------------------------------------------------------------------
// threefry2x32 — matches JAX bit-for-bit (partitionable mode)
// ---------------------------------------------------------------------------
__device__ __forceinline__ void tf2x32(unsigned k0, unsigned k1,
                                       unsigned x0, unsigned x1,
                                       unsigned &o0, unsigned &o1) {
  unsigned ks2 = k0 ^ k1 ^ 0x1BD11BDAu;
  x0 += k0; x1 += k1;
#define TFR(r) { x0 += x1; x1 = (x1 << (r)) | (x1 >> (32 - (r))); x1 ^= x0; }
  TFR(13) TFR(15) TFR(26) TFR(6)
  x0 += k1;  x1 += ks2 + 1u;
  TFR(17) TFR(29) TFR(16) TFR(24)
  x0 += ks2; x1 += k0 + 2u;
  TFR(13) TFR(15) TFR(26) TFR(6)
  x0 += k0;  x1 += k1 + 3u;
  TFR(17) TFR(29) TFR(16) TFR(24)
  x0 += k1;  x1 += ks2 + 4u;
  TFR(13) TFR(15) TFR(26) TFR(6)
  x0 += ks2; x1 += k0 + 5u;
#undef TFR
  o0 = x0; o1 = x1;
}

__device__ __forceinline__ unsigned pbits32(unsigned k0, unsigned k1, unsigned i) {
  unsigned o0, o1; tf2x32(k0, k1, 0u, i, o0, o1); return o0 ^ o1;
}
__device__ __forceinline__ unsigned long long pbits64(unsigned k0, unsigned k1, unsigned i) {
  unsigned o0, o1; tf2x32(k0, k1, 0u, i, o0, o1);
  return (((unsigned long long)o0) << 32) | o1;
}

extern __shared__ unsigned char s_raw[];

// ---------------------------------------------------------------------------
// Kernel 1: fused start + centers. 10 blocks; block c owns node range
// [c*20000, (c+1)*20000) (classes are contiguous arange), zeroes its range,
// then does rank-based center selection (validated bit-exact in R3/R5/R7).
// ---------------------------------------------------------------------------
__global__ __launch_bounds__(1024) void k_centers_start(const void* edge, long long E) {
  unsigned long long* skey = (unsigned long long*)s_raw;       // CCAP*8
  unsigned*           sjdx = (unsigned*)(skey + CCAP);         // CCAP*4
  unsigned*           hist = sjdx + CCAP;                      // CCAP*4
  __shared__ unsigned s_cnt;
  __shared__ int      s_bad, s_T;
  __shared__ unsigned part[1024];

  int c = blockIdx.x, tid = threadIdx.x;
  int base = c * IDS_PER_CLS;

  // zero this block's node range + hist stripe
  for (int j = tid; j < IDS_PER_CLS; j += 1024) {
    int n = base + j;
    g_probs[n] = 0.f; g_center[n] = 0; g_retained[n] = 0; g_nbr[n] = 0;
  }
  for (int i = c * 1024 + tid; i < 65536; i += N_CLS * 1024) g_hist[i] = 0;

  // dtype probe (each block independently, deterministic)
  if (tid == 0) s_bad = 0;
  if (tid == 0) s_cnt = 0;
  __syncthreads();
  long long lim = (E < 128) ? E : 128;
  if (tid < 128 && (long long)tid < lim) {
    long long v = ((const long long*)edge)[tid];
    if (v < 0 || v >= N_NODES) atomicOr(&s_bad, 1);
  }
  for (int b = tid; b < CCAP; b += 1024) hist[b] = 0;
  __syncthreads();
  int is64 = s_bad ? 0 : 1;

  // key splits (each thread computes locally; block 0 publishes for later kernels)
  unsigned kc0, kc1;
  tf2x32(0u, 42u, 0u, 0u, kc0, kc1);
  if (c == 0 && tid == 0) {
    unsigned o0, o1;
    g_ctrl.keys[0] = kc0; g_ctrl.keys[1] = kc1;
    tf2x32(0u, 42u, 0u, 1u, o0, o1); g_ctrl.keys[2] = o0; g_ctrl.keys[3] = o1;
    tf2x32(0u, 42u, 0u, 2u, o0, o1); g_ctrl.keys[4] = o0; g_ctrl.keys[5] = o1;
    g_ctrl.is64 = is64; g_ctrl.cand_n = 0;
    g_done[0] = 0; g_done[1] = 0; g_done[2] = 0; g_done[3] = 0;
  }

  // per-element uniform keys for this class
  for (int j = tid; j < IDS_PER_CLS; j += 1024) {
    unsigned m = (unsigned)(base + j);
    unsigned long long key; unsigned b;
    if (is64) {
      unsigned long long mant = pbits64(kc0, kc1, m) >> 12;   // u = mant*2^-52
      key = mant; b = (unsigned)(mant >> 40);
    } else {
      unsigned man = pbits32(kc0, kc1, m) >> 9;               // u = man*2^-23
      key = (((unsigned long long)man) << 32) | (unsigned)j;
      b = man >> 11;
    }
    g_keys[m] = key;
    atomicAdd(&hist[b], 1u);
  }
  __syncthreads();

  // ascending threshold via parallel prefix scan (chunk = 4 buckets/thread)
  unsigned mysum = 0;
  for (int b = tid * 4; b < tid * 4 + 4; b++) mysum += hist[b];
  part[tid] = mysum; __syncthreads();
  for (int off = 1; off < 1024; off <<= 1) {
    unsigned v = part[tid];
    if (tid >= off) v += part[tid - off];
    __syncthreads(); part[tid] = v; __syncthreads();
  }
  unsigned P = part[tid];
  if (P >= CENTER_BUDGET && P - mysum < CENTER_BUDGET) {
    unsigned acc = P - mysum; int T = tid * 4 + 3;
    for (int b = tid * 4; b < tid * 4 + 4; b++) {
      acc += hist[b];
      if (acc >= CENTER_BUDGET) { T = b; break; }
    }
    s_T = T;
  }
  __syncthreads();
  int T = s_T;

  // collect candidates (bucket <= T), then rank-select (cnt ~2005)
  for (int j = tid; j < IDS_PER_CLS; j += 1024) {
    int m = base + j;
    unsigned long long key = g_keys[m];
    unsigned b = is64 ? (unsigned)(key >> 40) : (unsigned)(key >> 43);
    if ((int)b <= T) {
      unsigned pos = atomicAdd(&s_cnt, 1u);
      if (pos < CCAP) { skey[pos] = key; sjdx[pos] = (unsigned)j; }
    }
  }
  __syncthreads();
  int cnt = (int)((s_cnt < CCAP) ? s_cnt : CCAP);

  for (int p = tid; p < cnt; p += 1024) {
    unsigned long long k = skey[p];
    unsigned j = sjdx[p];
    int rank = 0;
    for (int i = 0; i < cnt; i++) {
      unsigned long long ki = skey[i];
      unsigned ji = sjdx[i];
      rank += (ki < k) || (ki == k && ji < j);
    }
    if (rank < CENTER_BUDGET) {
      int node = base + (int)j;
      g_center_nodes[c * CENTER_BUDGET + rank] = node;
      g_center[node] = 1;
      g_retained[node] = 1;
    }
  }
}

// ---------------------------------------------------------------------------
// Kernel 2: fused edge pass (degree segment-sum + neighbor mask), 4/thread.
// ---------------------------------------------------------------------------
__global__ __launch_bounds__(256) void k_edges(const void* edge, const float* w, long long E) {
  long long base = ((long long)blockIdx.x * 256 + threadIdx.x) * 4;
  if (base >= E) return;
  int is64 = g_ctrl.is64;
  if (base + 3 < E) {
    int s[4], d[4];
    if (is64) {
      const ulonglong2* ps = (const ulonglong2*)((const long long*)edge + base);
      const ulonglong2* pd = (const ulonglong2*)((const long long*)edge + E + base);
      ulonglong2 s01 = ps[0], s23 = ps[1];
      ulonglong2 d01 = pd[0], d23 = pd[1];
      s[0]=(int)s01.x; s[1]=(int)s01.y; s[2]=(int)s23.x; s[3]=(int)s23.y;
      d[0]=(int)d01.x; d[1]=(int)d01.y; d[2]=(int)d23.x; d[3]=(int)d23.y;
    } else {
      const int4* ps = (const int4*)((const int*)edge + base);
      const int4* pd = (const int4*)((const int*)edge + E + base);
      int4 sv = ps[0], dv = pd[0];
      s[0]=sv.x; s[1]=sv.y; s[2]=sv.z; s[3]=sv.w;
      d[0]=dv.x; d[1]=dv.y; d[2]=dv.z; d[3]=dv.w;
    }
    float4 wv = *(const float4*)(w + base);
    atomicAdd(&g_probs[d[0]], wv.x);
    atomicAdd(&g_probs[d[1]], wv.y);
    atomicAdd(&g_probs[d[2]], wv.z);
    atomicAdd(&g_probs[d[3]], wv.w);
    unsigned char c0 = g_center[s[0]], c1 = g_center[s[1]];
    unsigned char c2 = g_center[s[2]], c3 = g_center[s[3]];
    if (c0) g_nbr[d[0]] = 1;
    if (c1) g_nbr[d[1]] = 1;
    if (c2) g_nbr[d[2]] = 1;
    if (c3) g_nbr[d[3]] = 1;
  } else {
    for (long long i = base; i < E; i++) {
      int s, d;
      if (is64) {
        const long long* p = (const long long*)edge;
        s = (int)p[i]; d = (int)p[E + i];
      } else {
        const int* p = (const int*)edge;
        s = p[i]; d = p[E + i];
      }
      atomicAdd(&g_probs[d], w[i]);
      if (g_center[s]) g_nbr[d] = 1;
    }
  }
}

// ---------------------------------------------------------------------------
// Kernel 3 (x2): hop keys (candidate-skip) + lastblock threshold selection.
// ---------------------------------------------------------------------------
__global__ __launch_bounds__(1024) void k_build(int h) {
  __shared__ unsigned part[1024];
  __shared__ unsigned hloc[64 * 16];   // unused placeholder keeps smem small
  (void)hloc;
  __shared__ unsigned s_last;
  int n = blockIdx.x * blockDim.x + threadIdx.x;
  if (n < N_NODES) {
    unsigned long long kk = 0;
    bool cand = g_nbr[n] && !g_retained[n];
    if (cand) {
      unsigned kh0 = g_ctrl.keys[2 + 2 * h], kh1 = g_ctrl.keys[3 + 2 * h];
      unsigned bits = pbits32(kh0, kh1, (unsigned)n);
      float ur = __uint_as_float((bits >> 9) | 0x3f800000u) - 1.0f;
      float u  = fmaxf(1.17549435e-38f, ur + 1.17549435e-38f);
      float g  = -logf(-logf(u));
      float v  = logf(g_probs[n]) + g;
      if (isfinite(v)) {
        unsigned b   = __float_as_uint(v);
        unsigned ord = b ^ ((b & 0x80000000u) ? 0xFFFFFFFFu : 0x80000000u);
        kk = (((unsigned long long)ord) << 32) | (0xFFFFFFFFu - (unsigned)n);
        atomicAdd(&g_hist[(unsigned)(kk >> 48)], 1u);
      }
    }
    g_keys[n] = kk;
  }

  // lastblock: threshold over 65536-digit histogram (parallel suffix scan)
  __syncthreads();
  if (threadIdx.x == 0) {
    __threadfence();
    s_last = (atomicAdd(&g_done[2 * h], 1u) == gridDim.x - 1) ? 1u : 0u;
  }
  __syncthreads();
  if (!s_last) return;
  __threadfence();

  int tid = threadIdx.x;
  unsigned mysum = 0;
  #pragma unroll 8
  for (int b = tid * 64; b < tid * 64 + 64; b++) mysum += g_hist[b];
  part[tid] = mysum; __syncthreads();
  for (int off = 1; off < 1024; off <<= 1) {
    unsigned v = part[tid];
    if (tid + off < 1024) v += part[tid + off];
    __syncthreads(); part[tid] = v; __syncthreads();
  }
  unsigned total = part[0];
  unsigned need = (total < HOP_BUDGET) ? total : HOP_BUDGET;
  if (tid == 0 && need == 0) {
    g_ctrl.thrT = 0xFFFFFFFFu; g_ctrl.need2 = 0; g_ctrl.take_all = 0;
    g_ctrl.cand_n = 0;
  }
  if (need != 0) {
    unsigned S = part[tid];
    if (S >= need && S - mysum < need) {       // unique crossing chunk
      unsigned acc = S - mysum;                // count in digits above this chunk
      for (int b = tid * 64 + 63; b >= tid * 64; b--) {
        unsigned hb = g_hist[b];
        if (acc + hb >= need) {
          g_ctrl.thrT = (unsigned)b;
          unsigned need2 = need - acc;
          g_ctrl.need2 = need2;
          g_ctrl.take_all = (need2 >= hb) ? 1u : 0u;
          g_ctrl.cand_n = 0;
          break;
        }
        acc += hb;
      }
    }
  }
}

// ---------------------------------------------------------------------------
// Kernel 4 (x2): scatter winners + boundary collect + hist re-zero;
// lastblock: two-level refine on boundary bucket (bits 47:36) + rank.
// ---------------------------------------------------------------------------
__global__ __launch_bounds__(1024) void k_scatter(int h) {
  __shared__ unsigned hist2[4096];
  __shared__ unsigned part[1024];
  __shared__ unsigned s_last, s_scnt;
  __shared__ int      s_T2;
  __shared__ unsigned s_need3;
  __shared__ unsigned long long skey[4096];

  int n = blockIdx.x * blockDim.x + threadIdx.x;
  unsigned T = g_ctrl.thrT;
  unsigned take_all = g_ctrl.take_all;
  if (n < 65536) g_hist[n] = 0;
  if (n < N_NODES) {
    unsigned long long kk = g_keys[n];
    if (kk) {
      unsigned dg = (unsigned)(kk >> 48);
      if (dg > T) {
        g_retained[n] = 1;
      } else if (dg == T) {
        if (take_all) {
          g_retained[n] = 1;
        } else {
          unsigned pos = atomicAdd(&g_ctrl.cand_n, 1u);
          if (pos < CAND_CAP) g_cand[pos] = kk;
        }
      }
    }
  }

  __syncthreads();
  if (threadIdx.x == 0) {
    __threadfence();
    s_last = (atomicAdd(&g_done[2 * h + 1], 1u) == gridDim.x - 1) ? 1u : 0u;
  }
  __syncthreads();
  if (!s_last) return;
  __threadfence();

  if (take_all) return;
  unsigned need2 = g_ctrl.need2;
  if (need2 == 0) return;
  unsigned cn = g_ctrl.cand_n;
  int cnt = (int)((cn < CAND_CAP) ? cn : CAND_CAP);
  int tid = threadIdx.x;

  for (int b = tid; b < 4096; b += 1024) hist2[b] = 0;
  if (tid == 0) s_scnt = 0;
  __syncthreads();
  for (int i = tid; i < cnt; i += 1024)
    atomicAdd(&hist2[(unsigned)(g_cand[i] >> 36) & 0xFFFu], 1u);
  __syncthreads();

  // descending suffix scan over 4096 (chunk = 4/thread, high-to-low in chunk)
  unsigned mysum = 0;
  for (int b = tid * 4; b < tid * 4 + 4; b++) mysum += hist2[b];
  part[tid] = mysum; __syncthreads();
  for (int off = 1; off < 1024; off <<= 1) {
    unsigned v = part[tid];
    if (tid + off < 1024) v += part[tid + off];
    __syncthreads(); part[tid] = v; __syncthreads();
  }
  unsigned S = part[tid];
  if (S >= need2 && S - mysum < need2) {
    unsigned acc = S - mysum; int T2 = tid * 4;
    unsigned n3 = need2;
    for (int b = tid * 4 + 3; b >= tid * 4; b--) {
      unsigned hb = hist2[b];
      if (acc + hb >= need2) { T2 = b; n3 = need2 - acc; break; }
      acc += hb;
    }
    s_T2 = T2; s_need3 = n3;
  }
  __syncthreads();
  int T2 = s_T2;
  unsigned need3 = s_need3;

  for (int i = tid; i < cnt; i += 1024) {
    unsigned long long k = g_cand[i];
    int d2 = (int)((k >> 36) & 0xFFFu);
    if (d2 > T2) {
      g_retained[0xFFFFFFFFu - (unsigned)(k & 0xFFFFFFFFu)] = 1;
    } else if (d2 == T2) {
      unsigned p = atomicAdd(&s_scnt, 1u);
      if (p < 4096) skey[p] = k;
    }
  }
  __syncthreads();
  int c2 = (int)((s_scnt < 4096u) ? s_scnt : 4096u);

  for (int p = tid; p < c2; p += 1024) {
    unsigned long long myk = skey[p];
    int rank = 0;
    for (int i = 0; i < c2; i++)
      rank += (skey[i] > myk);                 // keys unique (idx in low bits)
    if (rank < (int)need3)
      g_retained[0xFFFFFFFFu - (unsigned)(myk & 0xFFFFFFFFu)] = 1;
  }
}

// ---------------------------------------------------------------------------
// Output: f32 [center_nodes | retained | masked_probs]; branch on out_size.
// ---------------------------------------------------------------------------
__global__ void k_out(float* out, long long out_size) {
  long long i = (long long)blockIdx.x * blockDim.x + threadIdx.x;
  if (i >= out_size) return;
  float v;
  if (out_size == 420000) {
    if (i < 20000)        v = (float)g_center_nodes[i];
    else if (i < 220000)  v = g_retained[i - 20000] ? 1.f : 0.f;
    else                  v = g_retained[i - 220000] ? g_probs[i - 220000] : 0.f;
  } else if (out_size == 400000) {
    if (i < 200000)       v = g_retained[i] ? 1.f : 0.f;
    else                  v = g_retained[i - 200000] ? g_probs[i - 200000] : 0.f;
  } else if (out_size == 200000) {
    v = g_retained[i] ? g_probs[i] : 0.f;
  } else if (out_size == 20000) {
    v = (float)g_center_nodes[i];
  } else {
    v = 0.f;
  }
  out[i] = v;
}

// ---------------------------------------------------------------------------
extern "C" void kernel_launch(void* const* d_in, const int* in_sizes, int n_in,
                              void* d_out, int out_size) {
  const void* edge = d_in[0];
  const float* w = (const float*)d_in[1];
  long long E = (long long)in_sizes[0] / 2;

  cudaFuncSetAttribute(k_centers_start, cudaFuncAttributeMaxDynamicSharedMemorySize,
                       CCAP * 8 + CCAP * 4 + CCAP * 4);

  k_centers_start<<<N_CLS, 1024, CCAP * 8 + CCAP * 4 + CCAP * 4>>>(edge, E);
  k_edges<<<(unsigned)((E + 1023) / 1024), 256>>>(edge, w, E);
  for (int h = 0; h < 2; h++) {
    k_build<<<NODE_BLOCKS, 1024>>>(h);
    k_scatter<<<NODE_BLOCKS, 1024>>>(h);
  }
  k_out<<<((long long)out_size + 255) / 256, 256>>>((float*)d_out, (long long)out_size);
}